// round 2
// baseline (speedup 1.0000x reference)
#include <cuda_runtime.h>
#include <math.h>

// ---------------- sizes ----------------
#define BN_  2048
#define T_   200
#define CH_  64
#define H_   120

// ---------------- device scratch (static; no runtime allocation) ----------------
__device__ __align__(16) float g_p[BN_*8*T_];        // conv2 projection of elu(conv1) [b][o][t]
__device__ __align__(16) float g_y2[BN_*8*T_];       // elu(conv2 after BN1 fold)      [b][o][t]
__device__ __align__(16) float g_y4[BN_*8*50];       // elu(convp)                     [b][o][t]
__device__ __align__(16) float g_seq[8*10*BN_];      // LSTM inputs [k][t][b]
__device__ __align__(16) float g_feats[(size_t)8*BN_*240]; // [k][b][d]
__device__ __align__(16) float g_h[8*BN_];           // head outputs [k][b]
__device__ double g_S1[8];                           // conv1-ch: sum,sumsq pairs
__device__ double g_S2[16];
__device__ double g_S3[16];
__device__ double g_SO[16];
__device__ __align__(16) float g_whhT[8*120*120*4];  // [k][h][j][gate]
__device__ __align__(16) float g_wih4[8*120*4];
__device__ __align__(16) float g_bias4[8*120*4];
__device__ __align__(16) float g_wihb4[8*120*4];
__device__ __align__(16) float g_biasb4[8*120*4];
__device__ float g_bnlA[8*240];
__device__ float g_bnlB[8*240];

__device__ __forceinline__ float eluf(float v){ return v > 0.f ? v : expm1f(v); }
__device__ __forceinline__ float sigf(float v){ return 1.f / (1.f + __expf(-v)); }
__device__ __forceinline__ float tanh_f(float v){
  // tanh(x) = 1 - 2/(exp(2x)+1); __expf saturates to inf/0 at extremes -> correct +-1
  return 1.f - 2.f / (__expf(2.f * v) + 1.f);
}

// ---------------- K0: zero stats ----------------
__global__ void k0(){
  int i = threadIdx.x;
  if (i < 8)  g_S1[i] = 0.0;
  if (i < 16){ g_S2[i] = 0.0; g_S3[i] = 0.0; g_SO[i] = 0.0; }
}

// ---------------- Kprep: repack LSTM weights ----------------
__global__ void kprep(const float* __restrict__ wih, const float* __restrict__ whh,
                      const float* __restrict__ bih, const float* __restrict__ bhh){
  int i0 = blockIdx.x * blockDim.x + threadIdx.x;
  int stride = gridDim.x * blockDim.x;
  const int totalW = 8*120*120*4;
  for (int idx = i0; idx < totalW; idx += stride){
    int gi = idx & 3;
    int r  = idx >> 2;
    int j  = r % 120;
    int r2 = r / 120;
    int h  = r2 % 120;
    int k  = r2 / 120;
    g_whhT[idx] = whh[(size_t)((k*2 + 0)*480 + gi*120 + j)*120 + h];
  }
  const int totalB = 8*120*4;
  for (int idx = i0; idx < totalB; idx += stride){
    int gi = idx & 3;
    int r  = idx >> 2;
    int j  = r % 120;
    int k  = r / 120;
    int row0 = (k*2 + 0)*480 + gi*120 + j;
    int row1 = (k*2 + 1)*480 + gi*120 + j;
    g_wih4[idx]   = wih[row0];
    g_bias4[idx]  = bih[row0] + bhh[row0];
    g_wihb4[idx]  = wih[row1];
    g_biasb4[idx] = bih[row1] + bhh[row1];
  }
}

// ---------------- K1: conv1 + ELU + BN1 stats + conv2-projection ----------------
// block = one batch element. 256 threads: (q = tid>>6) covers t range, ch = tid&63.
__global__ __launch_bounds__(256, 2) void k1(const float* __restrict__ x,
                                             const float* __restrict__ w1,
                                             const float* __restrict__ b1,
                                             const float* __restrict__ w2){
  extern __shared__ float sx[];       // 300*64 floats, zero-padded input
  __shared__ float ws[404];
  __shared__ float w2s[512];
  __shared__ float p_s[1600];
  __shared__ float red[512];
  int b = blockIdx.x, tid = threadIdx.x;
  for (int i = tid; i < 50*64; i += 256){ sx[i] = 0.f; sx[250*64 + i] = 0.f; }
  for (int i = tid; i < 200*64; i += 256) sx[50*64 + i] = x[(size_t)b*12800 + i];
  for (int i = tid; i < 404; i += 256) ws[i] = w1[i];
  for (int i = tid; i < 512; i += 256) w2s[i] = w2[i];
  for (int i = tid; i < 1600; i += 256) p_s[i] = 0.f;
  __syncthreads();

  int ch = tid & 63, q = tid >> 6, lane = tid & 31;
  float bb[4] = {b1[0], b1[1], b1[2], b1[3]};
  float s[4]  = {0.f,0.f,0.f,0.f};
  float s2[4] = {0.f,0.f,0.f,0.f};

  for (int tile = 0; tile < 5; tile++){
    int t0 = q*50 + tile*10;
    float acc[4][10];
    #pragma unroll
    for (int g = 0; g < 4; g++)
      #pragma unroll
      for (int tt = 0; tt < 10; tt++) acc[g][tt] = 0.f;
    const float* xp = sx + t0*64 + ch;
    for (int k = 0; k < 101; k++){
      float wa = ws[k], wbv = ws[101+k], wc = ws[202+k], wd = ws[303+k];
      #pragma unroll
      for (int tt = 0; tt < 10; tt++){
        float xv = xp[(tt + k) * 64];
        acc[0][tt] = fmaf(wa,  xv, acc[0][tt]);
        acc[1][tt] = fmaf(wbv, xv, acc[1][tt]);
        acc[2][tt] = fmaf(wc,  xv, acc[2][tt]);
        acc[3][tt] = fmaf(wd,  xv, acc[3][tt]);
      }
    }
    #pragma unroll
    for (int g = 0; g < 4; g++){
      #pragma unroll
      for (int tt = 0; tt < 10; tt++){
        float e = eluf(acc[g][tt] + bb[g]);
        s[g] += e; s2[g] += e * e;
        float v0 = e * w2s[(2*g)*64 + ch];
        float v1 = e * w2s[(2*g+1)*64 + ch];
        #pragma unroll
        for (int sh = 16; sh > 0; sh >>= 1){
          v0 += __shfl_down_sync(0xffffffffu, v0, sh);
          v1 += __shfl_down_sync(0xffffffffu, v1, sh);
        }
        if (lane == 0){
          atomicAdd(&p_s[(2*g)*200 + t0 + tt], v0);
          atomicAdd(&p_s[(2*g+1)*200 + t0 + tt], v1);
        }
      }
    }
  }
  __syncthreads();
  for (int i = tid; i < 1600; i += 256) g_p[(size_t)b*1600 + i] = p_s[i];
  for (int g = 0; g < 4; g++){
    red[tid] = s[g]; red[256 + tid] = s2[g];
    __syncthreads();
    for (int st = 128; st > 0; st >>= 1){
      if (tid < st){ red[tid] += red[tid + st]; red[256 + tid] += red[256 + tid + st]; }
      __syncthreads();
    }
    if (tid == 0){
      atomicAdd(&g_S1[2*g],   (double)red[0]);
      atomicAdd(&g_S1[2*g+1], (double)red[256]);
    }
    __syncthreads();
  }
}

// ---------------- K2: BN1 fold + bias + ELU -> y2, BN2 stats ----------------
__global__ void k2(const float* __restrict__ w2, const float* __restrict__ b2,
                   const float* __restrict__ g1, const float* __restrict__ bt1){
  __shared__ float A[8], C[8];
  __shared__ float rs[16];
  int tid = threadIdx.x;
  if (tid < 8){
    int g = tid >> 1;
    double m = g_S1[2*g] / 26214400.0;
    double v = g_S1[2*g+1] / 26214400.0 - m*m;
    float a = g1[g] * (float)(1.0 / sqrt(v));
    float beta = bt1[g] - (float)m * a;
    float wsum = 0.f;
    for (int c = 0; c < 64; c++) wsum += w2[tid*64 + c];
    A[tid] = a; C[tid] = beta * wsum + b2[tid];
    rs[tid] = 0.f; rs[8 + tid] = 0.f;
  }
  __syncthreads();
  float ls[8] = {0.f,0.f,0.f,0.f,0.f,0.f,0.f,0.f};
  float lq[8] = {0.f,0.f,0.f,0.f,0.f,0.f,0.f,0.f};
  const int total = BN_*8*T_;
  for (int i = blockIdx.x*blockDim.x + tid; i < total; i += gridDim.x*blockDim.x){
    int o = (i / 200) & 7;
    float e = eluf(A[o] * g_p[i] + C[o]);
    g_y2[i] = e;
    ls[o] += e; lq[o] += e * e;
  }
  #pragma unroll
  for (int o = 0; o < 8; o++){ atomicAdd(&rs[o], ls[o]); atomicAdd(&rs[8+o], lq[o]); }
  __syncthreads();
  if (tid < 8){
    atomicAdd(&g_S2[2*tid],   (double)rs[tid]);
    atomicAdd(&g_S2[2*tid+1], (double)rs[8+tid]);
  }
}

// ---------------- K3: BN2 + pool4 + conv3 + ELU + convp + ELU -> y4, BN3 stats ----------------
__global__ void k3(const float* __restrict__ w3, const float* __restrict__ b3,
                   const float* __restrict__ wp, const float* __restrict__ bp,
                   const float* __restrict__ g2, const float* __restrict__ bt2){
  __shared__ float yb[1600];
  __shared__ float ppad[8][80];
  __shared__ float o3[8][50];
  __shared__ float A2[8], C2[8];
  __shared__ float w3s[200];
  __shared__ float wps[64];
  __shared__ float rs[16];
  int b = blockIdx.x, tid = threadIdx.x;
  if (tid < 8){
    double m = g_S2[2*tid] / 409600.0;
    double v = g_S2[2*tid+1] / 409600.0 - m*m;
    float a = g2[tid] * (float)(1.0 / sqrt(v));
    A2[tid] = a; C2[tid] = bt2[tid] - (float)m * a;
    rs[tid] = 0.f; rs[8 + tid] = 0.f;
  }
  for (int i = tid; i < 200; i += 256) w3s[i] = w3[i];
  if (tid < 64) wps[tid] = wp[tid];
  for (int i = tid; i < 640; i += 256) ((float*)ppad)[i] = 0.f;
  __syncthreads();
  for (int i = tid; i < 1600; i += 256){
    int o = i / 200;
    yb[i] = A2[o] * g_y2[(size_t)b*1600 + i] + C2[o];
  }
  __syncthreads();
  for (int i = tid; i < 400; i += 256){
    int o = i / 50, t = i % 50;
    const float* yo = &yb[o*200 + 4*t];
    ppad[o][12 + t] = fmaxf(fmaxf(yo[0], yo[1]), fmaxf(yo[2], yo[3]));
  }
  __syncthreads();
  for (int i = tid; i < 400; i += 256){
    int o = i / 50, t = i % 50;
    float acc = b3[o];
    #pragma unroll
    for (int k = 0; k < 25; k++) acc = fmaf(w3s[o*25 + k], ppad[o][t + k], acc);
    o3[o][t] = eluf(acc);
  }
  __syncthreads();
  for (int i = tid; i < 400; i += 256){
    int o = i / 50, t = i % 50;
    float acc = bp[o];
    #pragma unroll
    for (int c = 0; c < 8; c++) acc = fmaf(wps[o*8 + c], o3[c][t], acc);
    float e = eluf(acc);
    g_y4[(size_t)b*400 + i] = e;
    atomicAdd(&rs[o], e); atomicAdd(&rs[8+o], e*e);
  }
  __syncthreads();
  if (tid < 8){
    atomicAdd(&g_S3[2*tid],   (double)rs[tid]);
    atomicAdd(&g_S3[2*tid+1], (double)rs[8+tid]);
  }
}

// ---------------- K4: BN3 affine + pool5 -> g_seq[k][t][b] ----------------
__global__ void k4(const float* __restrict__ g3, const float* __restrict__ bt3){
  __shared__ float A3[8], C3[8];
  int tid = threadIdx.x;
  if (tid < 8){
    double m = g_S3[2*tid] / 102400.0;
    double v = g_S3[2*tid+1] / 102400.0 - m*m;
    float a = g3[tid] * (float)(1.0 / sqrt(v));
    A3[tid] = a; C3[tid] = bt3[tid] - (float)m * a;
  }
  __syncthreads();
  const int total = 8*10*BN_;
  for (int i = blockIdx.x*blockDim.x + tid; i < total; i += gridDim.x*blockDim.x){
    int b  = i & 2047;
    int ot = i >> 11;
    int o = ot / 10, t = ot % 10;
    const float* y = &g_y4[((size_t)b*8 + o)*50 + t*5];
    float m5 = A3[o]*y[0] + C3[o];
    #pragma unroll
    for (int j = 1; j < 5; j++) m5 = fmaxf(m5, A3[o]*y[j] + C3[o]);
    g_seq[i] = m5;
  }
}

// ---------------- K5: BiLSTM (fwd 10 steps + bwd 1 step) ----------------
// block = (branch k, 16-batch tile). 128 threads; thread j<120 owns hidden unit j.
__global__ __launch_bounds__(128, 4) void k5(){
  __shared__ __align__(16) float hs[2][120][16];
  __shared__ __align__(16) float xs[10][16];
  int k    = blockIdx.x >> 7;
  int tile = blockIdx.x & 127;
  int b0   = tile * 16;
  int tid  = threadIdx.x;
  for (int i = tid; i < 160; i += 128)
    xs[i >> 4][i & 15] = g_seq[((size_t)k*10 + (i >> 4))*2048 + b0 + (i & 15)];
  for (int i = tid; i < 120*16; i += 128) hs[0][i >> 4][i & 15] = 0.f;
  int j = tid;
  bool act = (j < 120);
  float4 xw = {0,0,0,0}, bs = {0,0,0,0};
  if (act){
    xw = *(const float4*)&g_wih4[(k*120 + j)*4];
    bs = *(const float4*)&g_bias4[(k*120 + j)*4];
  }
  float c[16];
  #pragma unroll
  for (int b = 0; b < 16; b++) c[b] = 0.f;
  __syncthreads();

  const float4* WT = (const float4*)g_whhT + (size_t)k*120*120;
  int cur = 0;
  for (int t = 0; t < 10; t++){
    if (act){
      float z0[16], z1[16], z2[16], z3[16];
      #pragma unroll
      for (int b = 0; b < 16; b++){
        float xv = xs[t][b];
        z0[b] = fmaf(xv, xw.x, bs.x);
        z1[b] = fmaf(xv, xw.y, bs.y);
        z2[b] = fmaf(xv, xw.z, bs.z);
        z3[b] = fmaf(xv, xw.w, bs.w);
      }
      #pragma unroll 2
      for (int h = 0; h < 120; h++){
        float4 w = WT[h*120 + j];
        const float4* hv = (const float4*)&hs[cur][h][0];
        float4 h0 = hv[0], h1 = hv[1], h2 = hv[2], h3 = hv[3];
        float hvf[16] = {h0.x,h0.y,h0.z,h0.w, h1.x,h1.y,h1.z,h1.w,
                         h2.x,h2.y,h2.z,h2.w, h3.x,h3.y,h3.z,h3.w};
        #pragma unroll
        for (int b = 0; b < 16; b++){
          float hb = hvf[b];
          z0[b] = fmaf(w.x, hb, z0[b]);
          z1[b] = fmaf(w.y, hb, z1[b]);
          z2[b] = fmaf(w.z, hb, z2[b]);
          z3[b] = fmaf(w.w, hb, z3[b]);
        }
      }
      #pragma unroll
      for (int b = 0; b < 16; b++){
        float ig = sigf(z0[b]);
        float fg = sigf(z1[b]);
        float gg = tanh_f(z2[b]);
        float og = sigf(z3[b]);
        c[b] = fg * c[b] + ig * gg;
        hs[cur ^ 1][j][b] = og * tanh_f(c[b]);
      }
    }
    __syncthreads();
    cur ^= 1;
  }

  if (act){
    #pragma unroll
    for (int b = 0; b < 16; b++)
      g_feats[((size_t)k*2048 + b0 + b)*240 + j] = hs[cur][j][b];
    // backward direction: single step from zero state on x[T-1]
    float4 xwb = *(const float4*)&g_wihb4[(k*120 + j)*4];
    float4 bsb = *(const float4*)&g_biasb4[(k*120 + j)*4];
    #pragma unroll
    for (int b = 0; b < 16; b++){
      float xv = xs[9][b];
      float zi = fmaf(xv, xwb.x, bsb.x);
      float zg = fmaf(xv, xwb.z, bsb.z);
      float zo = fmaf(xv, xwb.w, bsb.w);
      float cc = sigf(zi) * tanh_f(zg);
      g_feats[((size_t)k*2048 + b0 + b)*240 + 120 + j] = sigf(zo) * tanh_f(cc);
    }
  }
}

// ---------------- K6: bnl per-column stats + fold with head_w ----------------
__global__ void k6(const float* __restrict__ bnlg, const float* __restrict__ bnlb,
                   const float* __restrict__ hw){
  int col = blockIdx.x;          // 0..1919
  int k = col / 240, d = col % 240;
  int tid = threadIdx.x;
  __shared__ double r1[256], r2[256];
  double s = 0.0, q = 0.0;
  const float* base = g_feats + (size_t)k*2048*240 + d;
  for (int b = tid; b < 2048; b += 256){
    float v = base[(size_t)b*240];
    s += (double)v; q += (double)v * v;
  }
  r1[tid] = s; r2[tid] = q;
  __syncthreads();
  for (int st = 128; st > 0; st >>= 1){
    if (tid < st){ r1[tid] += r1[tid + st]; r2[tid] += r2[tid + st]; }
    __syncthreads();
  }
  if (tid == 0){
    double m = r1[0] / 2048.0;
    double v = r2[0] / 2048.0 - m*m;
    float a = bnlg[col] * (float)(1.0 / sqrt(v));
    float w = hw[col];
    g_bnlA[col] = a * w;
    g_bnlB[col] = (bnlb[col] - (float)m * a) * w;
  }
}

// ---------------- K7: head dot + ReLU, bno stats ----------------
__global__ void k7(const float* __restrict__ hb){
  int k  = blockIdx.x >> 3;
  int bt = blockIdx.x & 7;
  int tid = threadIdx.x;
  __shared__ float Aw[240];
  __shared__ float cs[256];
  for (int i = tid; i < 240; i += 256) Aw[i] = g_bnlA[k*240 + i];
  float cpart = 0.f;
  for (int i = tid; i < 240; i += 256) cpart += g_bnlB[k*240 + i];
  cs[tid] = cpart;
  __syncthreads();
  for (int st = 128; st > 0; st >>= 1){
    if (tid < st) cs[tid] += cs[tid + st];
    __syncthreads();
  }
  float cst = cs[0] + hb[k];
  int b = bt*256 + tid;
  const float* f = g_feats + ((size_t)k*2048 + b)*240;
  float acc = 0.f;
  #pragma unroll 4
  for (int d = 0; d < 240; d += 4){
    float4 fv = *(const float4*)&f[d];
    acc = fmaf(Aw[d],   fv.x, acc);
    acc = fmaf(Aw[d+1], fv.y, acc);
    acc = fmaf(Aw[d+2], fv.z, acc);
    acc = fmaf(Aw[d+3], fv.w, acc);
  }
  float h = fmaxf(acc + cst, 0.f);
  g_h[(size_t)k*2048 + b] = h;
  float s = h, q = h*h;
  #pragma unroll
  for (int sh = 16; sh > 0; sh >>= 1){
    s += __shfl_down_sync(0xffffffffu, s, sh);
    q += __shfl_down_sync(0xffffffffu, q, sh);
  }
  if ((tid & 31) == 0){
    atomicAdd(&g_SO[2*k],   (double)s);
    atomicAdd(&g_SO[2*k+1], (double)q);
  }
}

// ---------------- K8: bno + final linear + sigmoid ----------------
__global__ void k8(const float* __restrict__ bnog, const float* __restrict__ bnob,
                   const float* __restrict__ ow, const float* __restrict__ ob,
                   float* __restrict__ out){
  __shared__ float Ak[8], Ck[8];
  int tid = threadIdx.x;
  if (tid < 8){
    double m = g_SO[2*tid] / 2048.0;
    double v = g_SO[2*tid+1] / 2048.0 - m*m;
    float a = bnog[tid] * (float)(1.0 / sqrt(v));
    float cc = bnob[tid] - (float)m * a;
    Ak[tid] = a * ow[tid];
    Ck[tid] = cc * ow[tid];
  }
  __syncthreads();
  int b = blockIdx.x*blockDim.x + tid;
  if (b < 2048){
    float z = ob[0];
    #pragma unroll
    for (int k = 0; k < 8; k++)
      z = fmaf(Ak[k], g_h[(size_t)k*2048 + b], z + 0.f) + Ck[k] - Ck[k] + Ak[k]*0.f + (k == 0 ? 0.f : 0.f) + Ck[k];
    // note: the expression above reduces to z += Ak[k]*h + Ck[k]
    out[b] = sigf(z);
  }
}

// ---------------- launch ----------------
extern "C" void kernel_launch(void* const* d_in, const int* in_sizes, int n_in,
                              void* d_out, int out_size){
  const float* x       = (const float*)d_in[0];
  const float* conv1_w = (const float*)d_in[1];
  const float* conv1_b = (const float*)d_in[2];
  const float* bn1_g   = (const float*)d_in[3];
  const float* bn1_b   = (const float*)d_in[4];
  const float* conv2_w = (const float*)d_in[5];
  const float* conv2_b = (const float*)d_in[6];
  const float* bn2_g   = (const float*)d_in[7];
  const float* bn2_b   = (const float*)d_in[8];
  const float* conv3_w = (const float*)d_in[9];
  const float* conv3_b = (const float*)d_in[10];
  const float* convp_w = (const float*)d_in[11];
  const float* convp_b = (const float*)d_in[12];
  const float* bn3_g   = (const float*)d_in[13];
  const float* bn3_b   = (const float*)d_in[14];
  const float* lstm_wih= (const float*)d_in[15];
  const float* lstm_whh= (const float*)d_in[16];
  const float* lstm_bih= (const float*)d_in[17];
  const float* lstm_bhh= (const float*)d_in[18];
  const float* bnl_g   = (const float*)d_in[19];
  const float* bnl_b   = (const float*)d_in[20];
  const float* head_w  = (const float*)d_in[21];
  const float* head_b  = (const float*)d_in[22];
  const float* bno_g   = (const float*)d_in[23];
  const float* bno_b   = (const float*)d_in[24];
  const float* out_w   = (const float*)d_in[25];
  const float* out_b   = (const float*)d_in[26];
  float* out = (float*)d_out;

  cudaFuncSetAttribute(k1, cudaFuncAttributeMaxDynamicSharedMemorySize, 300*64*4);

  k0<<<1, 64>>>();
  kprep<<<512, 256>>>(lstm_wih, lstm_whh, lstm_bih, lstm_bhh);
  k1<<<BN_, 256, 300*64*4>>>(x, conv1_w, conv1_b, conv2_w);
  k2<<<512, 256>>>(conv2_w, conv2_b, bn2_g, bn2_b);
  k3<<<BN_, 256>>>(conv3_w, conv3_b, convp_w, convp_b, bn2_g, bn2_b);
  k4<<<320, 512>>>(bn3_g, bn3_b);
  k5<<<8*128, 128>>>();
  k6<<<1920, 256>>>(bnl_g, bnl_b, head_w);
  k7<<<64, 256>>>(head_b);
  k8<<<8, 256>>>(bno_g, bno_b, out_w, out_b, out);
}